// round 2
// baseline (speedup 1.0000x reference)
#include <cuda_runtime.h>

// Problem constants
#define B_I 3072   // 256*12 batched signals
#define N_N 2048   // signal length
#define M_M 512    // measurements
#define NITER 100

// Static device scratch (allocation-free rule)
__device__ float g_A [M_M * N_N];   // A[m][n]  = C[idx_m, n]
__device__ float g_AT[N_N * M_M];   // AT[n][m] = A[m][n]
__device__ float g_CT[N_N * N_N];   // CT[k][n] = C[n, k]  (for final idct)
__device__ float g_b [B_I * M_M];   // measurements * SCALE
__device__ float g_s [B_I * N_N];   // DCT coefficients (iterate)
__device__ float g_r [B_I * M_M];   // residual

// idxs may arrive as int64 or int32 depending on jax x64 config.
// If int32, reading element 0 as int64 packs (idx0, idx1); idx1 >= 1 (sorted
// unique), so the high 32 bits are nonzero. If genuinely int64, values < 2048
// so high bits are zero.
__device__ __forceinline__ int get_idx(const void* idxp, int m) {
    const long long* p64 = (const long long*)idxp;
    if ((p64[0] >> 32) == 0LL) return (int)p64[m];
    return ((const int*)idxp)[m];
}

// C[n,k] = w_k * cos(pi * k * (2n+1) / (2N)),  w_0 = sqrt(1/N), w_k = sqrt(2/N)
// Exact integer argument reduction: angle/pi = ((2n+1)*k mod 8192) / 4096.

__global__ void k_build_A(const void* idxs) {
    int tid = blockIdx.x * blockDim.x + threadIdx.x;
    if (tid >= M_M * N_N) return;
    int m = tid >> 11;          // / 2048
    int n = tid & 2047;
    int j = get_idx(idxs, m);
    int t = ((2 * j + 1) * n) & 8191;
    float w = (n == 0) ? rsqrtf((float)N_N) : sqrtf(2.0f / (float)N_N);
    float v = w * cospif((float)t * (1.0f / 4096.0f));
    g_A [m * N_N + n] = v;
    g_AT[n * M_M + m] = v;
}

__global__ void k_build_CT() {
    int tid = blockIdx.x * blockDim.x + threadIdx.x;
    if (tid >= N_N * N_N) return;
    int k = tid >> 11;
    int n = tid & 2047;
    int t = ((2 * n + 1) * k) & 8191;
    float w = (k == 0) ? rsqrtf((float)N_N) : sqrtf(2.0f / (float)N_N);
    g_CT[k * N_N + n] = w * cospif((float)t * (1.0f / 4096.0f));
}

__global__ void k_build_b(const float* __restrict__ x, const void* idxs) {
    int tid = blockIdx.x * blockDim.x + threadIdx.x;
    if (tid >= B_I * M_M) return;
    int i = tid >> 9;           // / 512
    int m = tid & 511;
    g_b[tid] = x[i * N_N + get_idx(idxs, m)] * 100.0f;
}

__global__ void k_zero_s() {
    int tid = blockIdx.x * blockDim.x + threadIdx.x;
    if (tid < B_I * N_N) g_s[tid] = 0.0f;
}

// ---------------------------------------------------------------------------
// Tiled fp32 GEMM: Cout[I x J] (+epilogue) from Aop[I x K] @ Bop[K x J].
// 128x128 tile, BK=16, 256 threads, 8x8 per thread.
// Thread columns are tx + 16*j (conflict-free Bs reads, coalesced C writes).
// MODE 0: Cout = acc - Extra            (residual)
// MODE 1: Cout = soft(Cout - acc, .05)  (ISTA update, in-place on s)
// MODE 2: Cout = acc * 0.01             (final idct / SCALE)
// All dims divide tile sizes exactly -> no bounds checks.
// ---------------------------------------------------------------------------
template<int MODE, int K, int J>
__device__ __forceinline__ void gemm_body(
    const float* __restrict__ Aop, const float* __restrict__ Bop,
    float* __restrict__ Cout, const float* __restrict__ Extra)
{
    __shared__ float As[16][129];   // pad 129 -> conflict-free k-major stores
    __shared__ float Bs[16][128];

    const int t  = threadIdx.x;
    const int tx = t & 15;
    const int ty = t >> 4;
    const int bx = blockIdx.x;
    const int by = blockIdx.y;

    const float* Ap = Aop + (by * 128) * K;
    const float* Bp = Bop + bx * 128;

    float acc[8][8];
    #pragma unroll
    for (int i = 0; i < 8; i++)
        #pragma unroll
        for (int j = 0; j < 8; j++) acc[i][j] = 0.0f;

    for (int k0 = 0; k0 < K; k0 += 16) {
        #pragma unroll
        for (int u = 0; u < 8; u++) {
            int idx = t + u * 256;
            int i = idx >> 4, k = idx & 15;
            As[k][i] = Ap[i * K + k0 + k];
        }
        #pragma unroll
        for (int u = 0; u < 8; u++) {
            int idx = t + u * 256;
            int k = idx >> 7, j = idx & 127;
            Bs[k][j] = Bp[(k0 + k) * J + j];
        }
        __syncthreads();
        #pragma unroll
        for (int k = 0; k < 16; k++) {
            float a[8], b[8];
            #pragma unroll
            for (int i = 0; i < 8; i++) a[i] = As[k][ty * 8 + i];
            #pragma unroll
            for (int j = 0; j < 8; j++) b[j] = Bs[k][tx + 16 * j];
            #pragma unroll
            for (int i = 0; i < 8; i++)
                #pragma unroll
                for (int j = 0; j < 8; j++)
                    acc[i][j] = fmaf(a[i], b[j], acc[i][j]);
        }
        __syncthreads();
    }

    const int row0 = by * 128 + ty * 8;
    const int col0 = bx * 128 + tx;
    #pragma unroll
    for (int i = 0; i < 8; i++) {
        #pragma unroll
        for (int j = 0; j < 8; j++) {
            int cidx = (row0 + i) * J + col0 + 16 * j;
            if (MODE == 0) {
                Cout[cidx] = acc[i][j] - Extra[cidx];
            } else if (MODE == 1) {
                float u = Cout[cidx] - acc[i][j];
                float v = fabsf(u) - 0.05f;
                Cout[cidx] = (v > 0.0f) ? copysignf(v, u) : 0.0f;
            } else {
                Cout[cidx] = acc[i][j] * 0.01f;
            }
        }
    }
}

__global__ void __launch_bounds__(256) gemm1_kernel() {
    // r = s @ AT - b     [3072x512] = [3072x2048] @ [2048x512]
    gemm_body<0, N_N, M_M>(g_s, g_AT, g_r, g_b);
}

__global__ void __launch_bounds__(256) gemm2_kernel() {
    // s = soft(s - r @ A, 0.05)   [3072x2048] += [3072x512] @ [512x2048]
    gemm_body<1, M_M, N_N>(g_r, g_A, g_s, nullptr);
}

__global__ void __launch_bounds__(256) final_kernel(float* out) {
    // out = (s @ CT) / SCALE      [3072x2048] = [3072x2048] @ [2048x2048]
    gemm_body<2, N_N, N_N>(g_s, g_CT, out, nullptr);
}

extern "C" void kernel_launch(void* const* d_in, const int* in_sizes, int n_in,
                              void* d_out, int out_size) {
    const float* x    = (const float*)d_in[0];
    const void*  idxs = d_in[1];
    float*       out  = (float*)d_out;

    k_build_A <<<(M_M * N_N + 255) / 256, 256>>>(idxs);
    k_build_CT<<<(N_N * N_N + 255) / 256, 256>>>();
    k_build_b <<<(B_I * M_M + 255) / 256, 256>>>(x, idxs);
    k_zero_s  <<<(B_I * N_N + 255) / 256, 256>>>();

    dim3 g1(M_M / 128, B_I / 128);   // (4, 24)
    dim3 g2(N_N / 128, B_I / 128);   // (16, 24)
    for (int it = 0; it < NITER; ++it) {
        gemm1_kernel<<<g1, 256>>>();
        gemm2_kernel<<<g2, 256>>>();
    }
    final_kernel<<<g2, 256>>>(out);
}

// round 4
// speedup vs baseline: 1.9913x; 1.9913x over previous
#include <cuda_runtime.h>
#include <cstdint>

// Problem constants
#define B_I 3072   // 256*12 batched signals
#define N_N 2048   // signal length
#define M_M 512    // measurements
#define NITER 100

// ---------------------------------------------------------------------------
// Global operand images, all in mma-fragment order (m16n8k8 tf32).
//
// A-image (row-blocks of 128, K-chunks of 32): per (bm, c) block: 8192 floats =
//   [hi plane 4096][lo plane 4096];  fi within plane:
//   fi = ((mt*4+ks)*32 + lane)*4 + reg
//   mt=(row>>4)&7, ks=(col>>3)&3, lane=((row&7)<<2)|(col&3),
//   reg=(row&8?1:0)+(col&4?2:0)
// B-image (col-blocks of 128, K-chunks of 32): per (bn, c) block: 2048 float4:
//   slot = (nt*4+ks)*32 + lane,  nt=(n>>3)&15, ks=(k>>3)&3,
//   lane=((n&7)<<2)|(k&3);  float4 = (hi_b0, hi_b1, lo_b0, lo_b1) where
//   b0 = elem(k), b1 = elem(k+4)
// ---------------------------------------------------------------------------
__device__ __align__(16) float g_simg[B_I * N_N * 2];   // s, A-image, NCH=64
__device__ __align__(16) float g_rimg[B_I * M_M * 2];   // r, A-image, NCH=16
__device__ __align__(16) float g_bimg[B_I * M_M];       // b, A-image hi layout
__device__ __align__(16) float g_B1[M_M * N_N * 2];     // gemm1 B (n=512,k=2048)
__device__ __align__(16) float g_B2[N_N * M_M * 2];     // gemm2 B (n=2048,k=512)
__device__ __align__(16) float g_B3[N_N * N_N * 2];     // final B (n=2048,k=2048)

// ---------------------------------------------------------------------------
// helpers
// ---------------------------------------------------------------------------
__device__ __forceinline__ uint32_t smem_u32(const void* p) {
    uint32_t a;
    asm("{ .reg .u64 t; cvta.to.shared.u64 t, %1; cvt.u32.u64 %0, t; }"
        : "=r"(a) : "l"(p));
    return a;
}

__device__ __forceinline__ float to_tf32(float x) {
    float r;
    asm("cvt.rna.tf32.f32 %0, %1;" : "=f"(r) : "f"(x));
    return r;
}

__device__ __forceinline__ void cp16(uint32_t saddr, const void* g) {
    asm volatile("cp.async.cg.shared.global [%0], [%1], 16;"
                 :: "r"(saddr), "l"(g) : "memory");
}
#define CP_COMMIT() asm volatile("cp.async.commit_group;" ::: "memory")
#define CP_WAIT1()  asm volatile("cp.async.wait_group 1;" ::: "memory")
#define CP_WAIT0()  asm volatile("cp.async.wait_group 0;" ::: "memory")

__device__ __forceinline__ uint4 lds128(uint32_t a) {
    uint4 v;
    asm volatile("ld.shared.v4.b32 {%0,%1,%2,%3}, [%4];"
                 : "=r"(v.x), "=r"(v.y), "=r"(v.z), "=r"(v.w) : "r"(a));
    return v;
}

__device__ __forceinline__ void mma8(float* c, const uint4 a,
                                     uint32_t b0, uint32_t b1) {
    asm volatile("mma.sync.aligned.m16n8k8.row.col.f32.tf32.tf32.f32 "
                 "{%0,%1,%2,%3}, {%4,%5,%6,%7}, {%8,%9}, {%0,%1,%2,%3};"
                 : "+f"(c[0]), "+f"(c[1]), "+f"(c[2]), "+f"(c[3])
                 : "r"(a.x), "r"(a.y), "r"(a.z), "r"(a.w), "r"(b0), "r"(b1));
}

// A-image float index within a (bm, c) plane
__device__ __forceinline__ int a_fi(int row, int col) {
    int mt = (row >> 4) & 7, ks = (col >> 3) & 3;
    int ln = ((row & 7) << 2) | (col & 3);
    int rg = ((row >> 3) & 1) | (((col >> 2) & 1) << 1);
    return ((mt * 4 + ks) * 32 + ln) * 4 + rg;
}

// idxs may be int64 or int32
__device__ __forceinline__ int get_idx(const void* idxp, int m) {
    const long long* p64 = (const long long*)idxp;
    if ((p64[0] >> 32) == 0LL) return (int)p64[m];
    return ((const int*)idxp)[m];
}

__device__ __forceinline__ float dct_w(int k) {
    return (k == 0) ? rsqrtf((float)N_N) : sqrtf(2.0f / (float)N_N);
}

// DCT matrix element generators (exact integer mod-8192 reduction)
// mode 1 (B1): n = measurement (use idx[n]), value = w_k cos(pi(2*idx_n+1)k/4096)
// mode 2 (B2): k = measurement (use idx[k]), value = w_n cos(pi(2*idx_k+1)n/4096)
// mode 3 (B3): value = w_k cos(pi(2n+1)k/4096)
__device__ __forceinline__ float bval(int mode, const void* idxs, int n, int k) {
    int t; float w;
    if (mode == 1)      { int j = get_idx(idxs, n); t = ((2*j+1)*k) & 8191; w = dct_w(k); }
    else if (mode == 2) { int j = get_idx(idxs, k); t = ((2*j+1)*n) & 8191; w = dct_w(n); }
    else                { t = ((2*n+1)*k) & 8191;                           w = dct_w(k); }
    return w * cospif((float)t * (1.0f / 4096.0f));
}

// ---------------------------------------------------------------------------
// setup kernels
// ---------------------------------------------------------------------------
__global__ void k_build_B(float4* img, const void* idxs, int mode, int NB, int NCH) {
    int id = blockIdx.x * blockDim.x + threadIdx.x;
    int total = NB * NCH * 2048;
    if (id >= total) return;
    int bn = id / (NCH * 2048);
    int rem = id - bn * (NCH * 2048);
    int c = rem >> 11;
    int rr = rem & 2047;
    int nt = rr >> 7, ks = (rr >> 5) & 3, lane = rr & 31;
    int n = bn * 128 + nt * 8 + (lane >> 2);
    int k0 = c * 32 + ks * 8 + (lane & 3);
    float v0 = bval(mode, idxs, n, k0);
    float v1 = bval(mode, idxs, n, k0 + 4);
    float h0 = to_tf32(v0), l0 = to_tf32(v0 - h0);
    float h1 = to_tf32(v1), l1 = to_tf32(v1 - h1);
    img[id] = make_float4(h0, h1, l0, l1);
}

__global__ void k_build_b(const float* __restrict__ x, const void* idxs) {
    int id = blockIdx.x * blockDim.x + threadIdx.x;
    if (id >= B_I * M_M) return;
    int i = id >> 9, m = id & 511;
    float v = x[(size_t)i * N_N + get_idx(idxs, m)] * 100.0f;
    g_bimg[((size_t)(i >> 7) * 16 + (m >> 5)) * 4096 + a_fi(i, m)] = v;
}

__global__ void k_zero_s() {
    int i = blockIdx.x * blockDim.x + threadIdx.x;
    const int n4 = B_I * N_N * 2 / 4;
    if (i < n4) ((float4*)g_simg)[i] = make_float4(0.f, 0.f, 0.f, 0.f);
}

// ---------------------------------------------------------------------------
// mma.sync tf32 split GEMM.  CTA 128x128, 8 warps (2x4), warp tile 64x32.
// K chunks of 32, double-buffered cp.async.  SMEM: 2 x (A 32KB + B 32KB).
// MODE 0: r-image = acc - b-image          (gemm1)
// MODE 1: s-image = soft(s_old - acc, .05) (gemm2, in-place)
// MODE 2: out = acc * 0.01                 (final, plain row-major)
// ---------------------------------------------------------------------------
#define SMEM_SZ 131072

template<int MODE, int KTOT, int JTOT>
__global__ void __launch_bounds__(256) mma_gemm(
    const float* __restrict__ Aimg, const float* __restrict__ Bimg,
    float* __restrict__ Out, const float* __restrict__ Baux)
{
    constexpr int NC = KTOT / 32;
    extern __shared__ char smem[];
    const uint32_t su = smem_u32(smem);
    const int tid = threadIdx.x, lane = tid & 31, w = tid >> 5;
    const int wm = w >> 2, wn = w & 3;
    const int bx = blockIdx.x, by = blockIdx.y;

    const float4* Ag = (const float4*)Aimg + (size_t)by * NC * 2048;
    const float4* Bg = (const float4*)Bimg + (size_t)bx * NC * 2048;

    float acc[4][4][4];
    #pragma unroll
    for (int i = 0; i < 4; i++)
        #pragma unroll
        for (int j = 0; j < 4; j++)
            #pragma unroll
            for (int e = 0; e < 4; e++) acc[i][j][e] = 0.0f;

    // prefetch chunk 0
    {
        const float4* a = Ag;
        const float4* b = Bg;
        #pragma unroll
        for (int u = 0; u < 8; u++)
            cp16(su + (tid + u * 256) * 16, a + tid + u * 256);
        #pragma unroll
        for (int u = 0; u < 8; u++)
            cp16(su + 32768 + (tid + u * 256) * 16, b + tid + u * 256);
        CP_COMMIT();
    }

    for (int c = 0; c < NC; c++) {
        if (c + 1 < NC) {
            uint32_t d = su + ((c + 1) & 1) * 65536;
            const float4* a = Ag + (size_t)(c + 1) * 2048;
            const float4* b = Bg + (size_t)(c + 1) * 2048;
            #pragma unroll
            for (int u = 0; u < 8; u++)
                cp16(d + (tid + u * 256) * 16, a + tid + u * 256);
            #pragma unroll
            for (int u = 0; u < 8; u++)
                cp16(d + 32768 + (tid + u * 256) * 16, b + tid + u * 256);
            CP_COMMIT();
            CP_WAIT1();
        } else {
            CP_WAIT0();
        }
        __syncthreads();

        const uint32_t sA = su + (c & 1) * 65536;
        const uint32_t sB = sA + 32768;
        #pragma unroll
        for (int ks = 0; ks < 4; ks++) {
            uint4 ahi[4], alo[4], bb[4];
            #pragma unroll
            for (int mt = 0; mt < 4; mt++) {
                uint32_t ad = sA + (((wm * 4 + mt) * 4 + ks) * 32 + lane) * 16;
                ahi[mt] = lds128(ad);
                alo[mt] = lds128(ad + 16384);
            }
            #pragma unroll
            for (int nt = 0; nt < 4; nt++)
                bb[nt] = lds128(sB + (((wn * 4 + nt) * 4 + ks) * 32 + lane) * 16);
            // product-major: 16 independent mma between accumulator reuse
            #pragma unroll
            for (int mt = 0; mt < 4; mt++)
                #pragma unroll
                for (int nt = 0; nt < 4; nt++)
                    mma8(acc[mt][nt], ahi[mt], bb[nt].x, bb[nt].y);
            #pragma unroll
            for (int mt = 0; mt < 4; mt++)
                #pragma unroll
                for (int nt = 0; nt < 4; nt++)
                    mma8(acc[mt][nt], ahi[mt], bb[nt].z, bb[nt].w);
            #pragma unroll
            for (int mt = 0; mt < 4; mt++)
                #pragma unroll
                for (int nt = 0; nt < 4; nt++)
                    mma8(acc[mt][nt], alo[mt], bb[nt].x, bb[nt].y);
        }
        __syncthreads();
    }

    // epilogue
    #pragma unroll
    for (int mt = 0; mt < 4; mt++) {
        #pragma unroll
        for (int nt = 0; nt < 4; nt++) {
            const int row0 = by * 128 + (wm * 4 + mt) * 16 + (lane >> 2);
            const int col0 = bx * 128 + (wn * 4 + nt) * 8 + 2 * (lane & 3);
            float* a = acc[mt][nt];
            #pragma unroll
            for (int e = 0; e < 4; e++) {
                const int row = row0 + (e >> 1) * 8;   // c2,c3 -> +8 rows
                const int col = col0 + (e & 1);        // c1,c3 -> +1 col
                float v = a[e];
                if (MODE == 2) {
                    Out[(size_t)row * JTOT + col] = v * 0.01f;
                } else {
                    constexpr int NCHO = (MODE == 0) ? (M_M / 32) : (N_N / 32);
                    const size_t blk = (size_t)(row >> 7) * NCHO + (col >> 5);
                    const int fi = a_fi(row, col);
                    if (MODE == 0) {
                        v -= Baux[blk * 4096 + fi];
                    } else {
                        const size_t base = blk * 8192;
                        float so = Out[base + fi] + Out[base + 4096 + fi];
                        float u = so - v;
                        float t = fabsf(u) - 0.05f;
                        v = (t > 0.0f) ? copysignf(t, u) : 0.0f;
                    }
                    const size_t base = blk * 8192;
                    float hi = to_tf32(v), lo = to_tf32(v - hi);
                    Out[base + fi] = hi;
                    Out[base + 4096 + fi] = lo;
                }
            }
        }
    }
}

extern "C" void kernel_launch(void* const* d_in, const int* in_sizes, int n_in,
                              void* d_out, int out_size) {
    const float* x    = (const float*)d_in[0];
    const void*  idxs = d_in[1];
    float*       out  = (float*)d_out;

    float *simg, *rimg, *bimg, *B1, *B2, *B3;
    cudaGetSymbolAddress((void**)&simg, g_simg);
    cudaGetSymbolAddress((void**)&rimg, g_rimg);
    cudaGetSymbolAddress((void**)&bimg, g_bimg);
    cudaGetSymbolAddress((void**)&B1, g_B1);
    cudaGetSymbolAddress((void**)&B2, g_B2);
    cudaGetSymbolAddress((void**)&B3, g_B3);

    cudaFuncSetAttribute(mma_gemm<0, N_N, M_M>,
                         cudaFuncAttributeMaxDynamicSharedMemorySize, SMEM_SZ);
    cudaFuncSetAttribute(mma_gemm<1, M_M, N_N>,
                         cudaFuncAttributeMaxDynamicSharedMemorySize, SMEM_SZ);
    cudaFuncSetAttribute(mma_gemm<2, N_N, N_N>,
                         cudaFuncAttributeMaxDynamicSharedMemorySize, SMEM_SZ);

    // build static operand images
    k_build_B<<<(4 * 64 * 2048 + 255) / 256, 256>>>((float4*)B1, idxs, 1, 4, 64);
    k_build_B<<<(16 * 16 * 2048 + 255) / 256, 256>>>((float4*)B2, idxs, 2, 16, 16);
    k_build_B<<<(16 * 64 * 2048 + 255) / 256, 256>>>((float4*)B3, idxs, 3, 16, 64);
    k_build_b<<<(B_I * M_M + 255) / 256, 256>>>(x, idxs);
    k_zero_s <<<(B_I * N_N * 2 / 4 + 255) / 256, 256>>>();

    dim3 g1(M_M / 128, B_I / 128);   // (4, 24)
    dim3 g2(N_N / 128, B_I / 128);   // (16, 24)
    for (int it = 0; it < NITER; ++it) {
        // r = s @ A^T - b   (output in gemm2's A-image layout)
        mma_gemm<0, N_N, M_M><<<g1, 256, SMEM_SZ>>>(simg, B1, rimg, bimg);
        // s = soft(s - r @ A, 0.05)  (output in gemm1's A-image layout)
        mma_gemm<1, M_M, N_N><<<g2, 256, SMEM_SZ>>>(rimg, B2, simg, nullptr);
    }
    // out = idct(s) / SCALE
    mma_gemm<2, N_N, N_N><<<g2, 256, SMEM_SZ>>>(simg, B3, out, nullptr);
}